// round 4
// baseline (speedup 1.0000x reference)
#include <cuda_runtime.h>
#include <cstdint>

#define TPB 256
#define BM 128
#define BN 128
#define BK 32
#define SPAD 36   // 32 + 4 pad: conflict-free fragment LDS, keeps 16B alignment

// Scratch (no cudaMalloc allowed): s[b,c] = ||center_c||^2 - 2 * f_b . c_c
__device__ float g_d2[16384 * 1000];
__device__ float g_c2[4096];

// ---------------- reductions ----------------
__device__ __forceinline__ float warpReduceSum(float v) {
    #pragma unroll
    for (int o = 16; o > 0; o >>= 1) v += __shfl_xor_sync(0xffffffffu, v, o);
    return v;
}
__device__ __forceinline__ float warpReduceMin(float v) {
    #pragma unroll
    for (int o = 16; o > 0; o >>= 1) v = fminf(v, __shfl_xor_sync(0xffffffffu, v, o));
    return v;
}
__device__ __forceinline__ float warpReduceMax(float v) {
    #pragma unroll
    for (int o = 16; o > 0; o >>= 1) v = fmaxf(v, __shfl_xor_sync(0xffffffffu, v, o));
    return v;
}

__device__ __forceinline__ float blockReduceSum(float v, float* red) {
    __syncthreads();
    v = warpReduceSum(v);
    int w = threadIdx.x >> 5, l = threadIdx.x & 31;
    if (l == 0) red[w] = v;
    __syncthreads();
    if (w == 0) {
        float x = (l < (int)(blockDim.x >> 5)) ? red[l] : 0.0f;
        x = warpReduceSum(x);
        if (l == 0) red[0] = x;
    }
    __syncthreads();
    return red[0];
}
__device__ __forceinline__ float blockReduceMin(float v, float* red) {
    __syncthreads();
    v = warpReduceMin(v);
    int w = threadIdx.x >> 5, l = threadIdx.x & 31;
    if (l == 0) red[w] = v;
    __syncthreads();
    if (w == 0) {
        float x = (l < (int)(blockDim.x >> 5)) ? red[l] : 3.4e38f;
        x = warpReduceMin(x);
        if (l == 0) red[0] = x;
    }
    __syncthreads();
    return red[0];
}
__device__ __forceinline__ float blockReduceMax(float v, float* red) {
    __syncthreads();
    v = warpReduceMax(v);
    int w = threadIdx.x >> 5, l = threadIdx.x & 31;
    if (l == 0) red[w] = v;
    __syncthreads();
    if (w == 0) {
        float x = (l < (int)(blockDim.x >> 5)) ? red[l] : -3.4e38f;
        x = warpReduceMax(x);
        if (l == 0) red[0] = x;
    }
    __syncthreads();
    return red[0];
}

// ---------------- softmax over classes ----------------
__global__ void __launch_bounds__(TPB) softmax_kernel(
    const float* __restrict__ P, float* __restrict__ out, int C)
{
    __shared__ float red[8];
    int b = blockIdx.x;
    const float* row = P + (size_t)b * C;
    float v[4];
    int cnt = 0;
    float mx = -3.4e38f;
    for (int i = threadIdx.x; i < C; i += TPB) {
        float x = row[i];
        v[cnt++] = x;
        mx = fmaxf(mx, x);
    }
    mx = blockReduceMax(mx, red);
    float s = 0.0f;
    #pragma unroll
    for (int j = 0; j < 4; j++) {
        if (j < cnt) { v[j] = __expf(v[j] - mx); s += v[j]; }
    }
    s = blockReduceSum(s, red);
    float inv = 1.0f / s;
    float* orow = out + (size_t)b * C;
    cnt = 0;
    for (int i = threadIdx.x; i < C; i += TPB) orow[i] = v[cnt++] * inv;
}

// ---------------- center norms ----------------
__global__ void __launch_bounds__(TPB) c2_kernel(const float* __restrict__ Cn, int D)
{
    __shared__ float red[8];
    int c = blockIdx.x;
    const float* row = Cn + (size_t)c * D;
    float s = 0.0f;
    for (int i = threadIdx.x; i < D; i += TPB) { float x = row[i]; s += x * x; }
    s = blockReduceSum(s, red);
    if (threadIdx.x == 0) g_c2[c] = s;
}

// ---------------- tf32 mma GEMM: s[b,c] = c2[c] - 2 * f_b . c_c ----------------
__device__ __forceinline__ void mma_tf32(float* c, const uint32_t* a, const uint32_t* b)
{
    asm volatile(
        "mma.sync.aligned.m16n8k8.row.col.f32.tf32.tf32.f32 "
        "{%0,%1,%2,%3},{%4,%5,%6,%7},{%8,%9},{%0,%1,%2,%3};\n"
        : "+f"(c[0]), "+f"(c[1]), "+f"(c[2]), "+f"(c[3])
        : "r"(a[0]), "r"(a[1]), "r"(a[2]), "r"(a[3]), "r"(b[0]), "r"(b[1]));
}

__global__ void __launch_bounds__(TPB) gemm_mindist_kernel(
    const float* __restrict__ F, const float* __restrict__ Cn,
    int Bsz, int C, int D)
{
    __shared__ float As[BM * SPAD];
    __shared__ float Bs[BN * SPAD];

    const int tid  = threadIdx.x;
    const int bm   = blockIdx.y * BM;
    const int bn   = blockIdx.x * BN;
    const int lane = tid & 31;
    const int warp = tid >> 5;
    const int wm   = warp & 3;   // 4 warps in M  -> 32 rows each
    const int wn   = warp >> 2;  // 2 warps in N  -> 64 cols each
    const int gr   = lane >> 2;
    const int tg   = lane & 3;

    float acc[2][8][4];
    #pragma unroll
    for (int mt = 0; mt < 2; mt++)
        #pragma unroll
        for (int nt = 0; nt < 8; nt++)
            #pragma unroll
            for (int k = 0; k < 4; k++) acc[mt][nt][k] = 0.0f;

    const int nk = D / BK;
    float4 ar[4], br[4];

    auto gload = [&](int kt) {
        #pragma unroll
        for (int j = 0; j < 4; j++) {
            int i  = tid + TPB * j;
            int r  = i >> 3;
            int c4 = (i & 7) * 4;
            ar[j] = *(const float4*)(F + (size_t)(bm + r) * D + kt * BK + c4);
            int brow = bn + r;
            if (brow < C)
                br[j] = *(const float4*)(Cn + (size_t)brow * D + kt * BK + c4);
            else
                br[j] = make_float4(0.f, 0.f, 0.f, 0.f);
        }
    };
    auto sstore = [&]() {
        #pragma unroll
        for (int j = 0; j < 4; j++) {
            int i  = tid + TPB * j;
            int r  = i >> 3;
            int c4 = (i & 7) * 4;
            *(float4*)&As[r * SPAD + c4] = ar[j];
            *(float4*)&Bs[r * SPAD + c4] = br[j];
        }
    };

    gload(0);
    sstore();
    __syncthreads();

    for (int kt = 0; kt < nk; kt++) {
        if (kt + 1 < nk) gload(kt + 1);

        #pragma unroll
        for (int ks = 0; ks < 4; ks++) {
            const int kk = ks * 8;
            uint32_t a[2][4];
            #pragma unroll
            for (int mt = 0; mt < 2; mt++) {
                const float* Ab = &As[(wm * 32 + mt * 16) * SPAD + kk];
                a[mt][0] = __float_as_uint(Ab[gr * SPAD + tg]);
                a[mt][1] = __float_as_uint(Ab[(gr + 8) * SPAD + tg]);
                a[mt][2] = __float_as_uint(Ab[gr * SPAD + tg + 4]);
                a[mt][3] = __float_as_uint(Ab[(gr + 8) * SPAD + tg + 4]);
            }
            uint32_t bb[8][2];
            #pragma unroll
            for (int nt = 0; nt < 8; nt++) {
                const float* Bb = &Bs[(wn * 64 + nt * 8) * SPAD + kk];
                bb[nt][0] = __float_as_uint(Bb[gr * SPAD + tg]);
                bb[nt][1] = __float_as_uint(Bb[gr * SPAD + tg + 4]);
            }
            #pragma unroll
            for (int mt = 0; mt < 2; mt++)
                #pragma unroll
                for (int nt = 0; nt < 8; nt++)
                    mma_tf32(acc[mt][nt], a[mt], bb[nt]);
        }
        __syncthreads();
        if (kt + 1 < nk) { sstore(); __syncthreads(); }
    }

    // epilogue: s = c2[c] - 2*cross
    #pragma unroll
    for (int mt = 0; mt < 2; mt++) {
        #pragma unroll
        for (int nt = 0; nt < 8; nt++) {
            int r0 = bm + wm * 32 + mt * 16 + gr;
            int c0 = bn + wn * 64 + nt * 8 + 2 * tg;
            if (c0 < C) {
                float cc = g_c2[c0];
                g_d2[(size_t)r0 * C + c0]       = cc - 2.0f * acc[mt][nt][0];
                g_d2[(size_t)(r0 + 8) * C + c0] = cc - 2.0f * acc[mt][nt][2];
            }
            if (c0 + 1 < C) {
                float cc = g_c2[c0 + 1];
                g_d2[(size_t)r0 * C + c0 + 1]       = cc - 2.0f * acc[mt][nt][1];
                g_d2[(size_t)(r0 + 8) * C + c0 + 1] = cc - 2.0f * acc[mt][nt][3];
            }
        }
    }
}

// ---------------- min + exact fp32 refinement + threshold mask ----------------
#define MARGIN 4.0f

__global__ void __launch_bounds__(TPB) minmask_kernel(
    const float* __restrict__ F, const float* __restrict__ Cn,
    const float* __restrict__ GS, float* __restrict__ mask, int C, int D)
{
    __shared__ float sfeat[2048];
    __shared__ float red[8];
    __shared__ int   s_cand[64];
    __shared__ int   s_ncand;

    const int b   = blockIdx.x;
    const int tid = threadIdx.x;

    float f2p = 0.0f;
    for (int i = tid; i < D; i += TPB) {
        float v = F[(size_t)b * D + i];
        if (i < 2048) sfeat[i] = v;
        f2p += v * v;
    }
    float f2 = blockReduceSum(f2p, red);

    const float* srow = g_d2 + (size_t)b * C;
    float mn = 3.4e38f;
    for (int i = tid; i < C; i += TPB) mn = fminf(mn, srow[i]);
    mn = blockReduceMin(mn, red);

    if (tid == 0) s_ncand = 0;
    __syncthreads();
    for (int i = tid; i < C; i += TPB) {
        if (srow[i] <= mn + MARGIN) {
            int j = atomicAdd(&s_ncand, 1);
            if (j < 64) s_cand[j] = i;
        }
    }
    __syncthreads();
    int nc = min(s_ncand, 64);

    // exact fp32 recompute of candidate distances (kills tf32 noise at the decision)
    float best = 3.4e38f;
    for (int j = 0; j < nc; j++) {
        int c = s_cand[j];
        const float* crow = Cn + (size_t)c * D;
        float dp = 0.0f;
        for (int i = tid; i < D; i += TPB) dp += sfeat[i] * crow[i];
        float dot = blockReduceSum(dp, red);
        best = fminf(best, g_c2[c] - 2.0f * dot);
    }

    if (tid == 0) {
        float d2   = f2 + best;
        float dist = sqrtf(fmaxf(d2, 0.0f));
        float T    = GS[0] + 1.5f * GS[1];
        mask[b] = (dist / (T + 1e-8f) > 1.0f) ? 1.0f : 0.0f;
    }
}

__global__ void fill_kernel(float* p, int n)
{
    int i = blockIdx.x * blockDim.x + threadIdx.x;
    if (i < n) p[i] = 0.0f;
}

// ---------------- launch ----------------
extern "C" void kernel_launch(void* const* d_in, const int* in_sizes, int n_in,
                              void* d_out, int out_size)
{
    const float* F  = (const float*)d_in[0];  // features  [B, D]
    const float* P  = (const float*)d_in[1];  // predictions [B, C]
    const float* Cn = (const float*)d_in[2];  // centers [C, D]
    const float* GS = (const float*)d_in[3];  // global_stats [2]

    const int B = in_sizes[4];            // known_labels length
    const int D = in_sizes[0] / B;
    const int C = in_sizes[1] / B;

    float* out   = (float*)d_out;
    float* mask  = out;                   // mask_novel first (return order)
    float* probs = out + B;               // probs second

    softmax_kernel<<<B, TPB>>>(P, probs, C);
    c2_kernel<<<C, TPB>>>(Cn, D);

    dim3 g((C + BN - 1) / BN, B / BM);    // B=16384 divisible by 128; D=2048 by 32
    gemm_mindist_kernel<<<g, TPB>>>(F, Cn, B, C, D);

    minmask_kernel<<<B, TPB>>>(F, Cn, GS, mask, C, D);

    long total = (long)B * C + B;
    if ((long)out_size > total) {
        long rem = (long)out_size - total;
        fill_kernel<<<(int)((rem + 255) / 256), 256>>>(out + total, (int)rem);
    }
}